// round 17
// baseline (speedup 1.0000x reference)
#include <cuda_runtime.h>
#include <cstdint>

// CausalMemoryAttention: B=16, S=4096, D=1024   (exact restructure, validated)
//   Q = query@Wq^T + bq ; qt = Q@Wk ; qbk = Q.bk
//   score[b,s] = (mb[b,s].qt[b] + qbk[b])/32 * tw[b,s],  tw = exp(-0.01*(ct-ts))
//   p = exp(score); attn = p/E; m = (sum p*mb)/E; attended = m@Wv^T + bv
// 4 launches:
//   k_qt2 (fused: redundant Q chunk + qt partials + qbk partials; tw) 128 blocks
//   k_main(268MB pass, R4 loop; qbk = sum of 16 partials; 55us/61%)   288 blocks
//   k_mid (m finalize + attn normalize)                                80 blocks
//   k_fin (attended GEMM)                                             128 blocks

#define B 16
#define S 4096
#define D 1024
#define D4 256
#define QT_SPLITS 16
#define CTAS_PER_B 18
#define NCTA_MAIN (B * CTAS_PER_B)        // 288 (single wave at 2 CTA/SM)
#define DEPTH 3
#define STAGE_ROWS 8
#define STAGE_F4 (STAGE_ROWS * D4)        // 2048 float4
#define STAGE_BYTES (STAGE_F4 * 16)       // 32 KB
#define SMEM_MAIN (DEPTH * STAGE_BYTES)   // 96 KB
#define SMEM_FIN (B * D * 4)              // 64 KB (all of m)

// -------- scratch (device globals; no dynamic allocation) --------
__device__ __align__(16) float g_qt_part[QT_SPLITS * B * D];
__device__ float g_qbk_part[16 * B];      // [d-chunk][b]
__device__ __align__(16) float g_tw[B * S];
__device__ __align__(16) float g_p[B * S];
__device__ __align__(16) float g_macc[NCTA_MAIN * D];
__device__ float g_Epart[NCTA_MAIN];
__device__ __align__(16) float g_m[B * D];

// ---------------- cp.async helpers ----------------
__device__ __forceinline__ void cp_async16(uint32_t smem, const void* gmem) {
    asm volatile("cp.async.cg.shared.global [%0], [%1], 16;"
                 :: "r"(smem), "l"(gmem) : "memory");
}
__device__ __forceinline__ void cp_commit() {
    asm volatile("cp.async.commit_group;" ::: "memory");
}
template <int N> __device__ __forceinline__ void cp_wait() {
    asm volatile("cp.async.wait_group %0;" :: "n"(N) : "memory");
}

// ============================================================
// k_qt2: 128 blocks x 256 threads. ONE preamble launch.
//   bid 0..63 : fused role. block = (e-tile et=bid&3 of 256, d-chunk
//     by=bid>>2 of 64). Recomputes Q[:, d-chunk] locally (shuffle-free,
//     staged transposed Wq tiles, pad 65 both-way conflict-free), adds
//     bq, then: qt partials (thread-per-e, 64x16 FMA vs coalesced Wk)
//     and (et==0) qbk partials g_qbk_part[by][b].
//   bid 64..127: tw-role. tw = exp(-0.01*(ct-ts)).
// ============================================================
__global__ __launch_bounds__(256) void k_qt2(
    const float* __restrict__ query, const float* __restrict__ Wq,
    const float* __restrict__ Wk, const float* __restrict__ bq,
    const float* __restrict__ bk,
    const float* __restrict__ ts, const float* __restrict__ ct)
{
    int bid = blockIdx.x, tid = threadIdx.x;

    if (bid < 64) {
        __shared__ float wt[64 * 65];     // wt[c][d_local], pad 65 (16.6KB)
        __shared__ float qs[16 * 64];     // qs[b][c]
        __shared__ float Qs[64 * 20];     // Qs[dl][b], pad 20

        int et = bid & 3, by = bid >> 2;
        int e = et * 256 + tid;
        int d0 = by * 64;
        int dl = tid & 63, bg = tid >> 6;  // bg 0..3 -> batches bg*4..bg*4+3

        // ---- redundant Q chunk: Q[b, d0..d0+63] over 16 c-chunks ----
        float accq[4] = {0.f, 0.f, 0.f, 0.f};
        for (int cc = 0; cc < 16; cc++) {
            int c0 = cc * 64;
            __syncthreads();              // wt/qs reuse fence
#pragma unroll
            for (int k = 0; k < 16; k++) {
                int i = k * 256 + tid;
                int row = i >> 6, col = i & 63;
                wt[col * 65 + row] = Wq[(size_t)(d0 + row) * D + c0 + col];
            }
            for (int i = tid; i < 1024; i += 256) {
                int b = i >> 6, c = i & 63;
                qs[b * 64 + c] = query[b * D + c0 + c];
            }
            __syncthreads();
#pragma unroll 8
            for (int c = 0; c < 64; c++) {
                float wv = wt[c * 65 + dl];
#pragma unroll
                for (int j = 0; j < 4; j++)
                    accq[j] += qs[(bg * 4 + j) * 64 + c] * wv;
            }
        }
        float bqv = bq[d0 + dl];
#pragma unroll
        for (int j = 0; j < 4; j++)
            Qs[dl * 20 + bg * 4 + j] = accq[j] + bqv;
        __syncthreads();

        // ---- qbk partial for this d-chunk (one e-tile block does it) ----
        if (et == 0 && tid < 16) {
            float s = 0.f;
#pragma unroll 16
            for (int d2 = 0; d2 < 64; d2++)
                s += Qs[d2 * 20 + tid] * bk[d0 + d2];
            g_qbk_part[by * 16 + tid] = s;
        }

        // ---- qt partials: thread per e, 64 x 16 FMA vs coalesced Wk ----
        float acc[16];
#pragma unroll
        for (int bb = 0; bb < 16; bb++) acc[bb] = 0.f;
#pragma unroll 8
        for (int dl2 = 0; dl2 < 64; dl2++) {
            float wv = Wk[(size_t)(d0 + dl2) * D + e];
            const float4* q4 = reinterpret_cast<const float4*>(&Qs[dl2 * 20]);
#pragma unroll
            for (int j = 0; j < 4; j++) {
                float4 qq = q4[j];
                acc[4 * j + 0] += qq.x * wv;
                acc[4 * j + 1] += qq.y * wv;
                acc[4 * j + 2] += qq.z * wv;
                acc[4 * j + 3] += qq.w * wv;
            }
        }
#pragma unroll
        for (int bb = 0; bb < 16; bb++)
            g_qt_part[(size_t)(by * 16 + bb) * D + e] = acc[bb];
    } else {
        // ---- tw-role ----
        int idx = (bid - 64) * 1024 + tid * 4;
        int b = idx >> 12;
        float curt = ct[b];
        float4 t = *reinterpret_cast<const float4*>(ts + idx);
        float4 w;
        w.x = __expf(-0.01f * (curt - t.x));
        w.y = __expf(-0.01f * (curt - t.y));
        w.z = __expf(-0.01f * (curt - t.z));
        w.w = __expf(-0.01f * (curt - t.w));
        *reinterpret_cast<float4*>(g_tw + idx) = w;
    }
}

// ============================================================
// k_main: streaming pass over memory_bank. FROZEN R4 loop (R14:
// 55.0us @ 61% DRAM, regs 118). Only delta: qbk = sum of 16 chunk
// partials (uniform scalar loads in the overlapped prologue).
// ============================================================
__global__ __launch_bounds__(256, 2) void k_main(
    const float* __restrict__ mb)
{
    extern __shared__ __align__(16) float4 sbuf[];   // DEPTH * STAGE_F4
    __shared__ float sE[8];

    int b = blockIdx.x / CTAS_PER_B;
    int j = blockIdx.x % CTAS_PER_B;
    int warp = threadIdx.x >> 5, lane = threadIdx.x & 31, tid = threadIdx.x;

    // 512 stages per batch split 8x29 + 10x28
    int nst = (j < 8) ? 29 : 28;
    int st0 = (j < 8) ? j * 29 : 232 + (j - 8) * 28;

    const float* gsrc = mb + (size_t)b * S * D + (size_t)st0 * STAGE_ROWS * D;
    uint32_t sb = (uint32_t)__cvta_generic_to_shared(sbuf);

    // ---- prologue: issue first DEPTH stages ----
    int issued = 0;
    for (; issued < DEPTH && issued < nst; issued++) {
        uint32_t dst = sb + (uint32_t)(issued % DEPTH) * STAGE_BYTES;
        const float* src = gsrc + (size_t)issued * STAGE_ROWS * D;
        for (int c = tid; c < STAGE_F4; c += 256)
            cp_async16(dst + (uint32_t)c * 16, src + (size_t)c * 4);
        cp_commit();
    }

    // ---- qt split-reduce (overlaps DRAM ramp) + qbk from partials ----
    float4 q[8];
#pragma unroll
    for (int k = 0; k < 8; k++) q[k] = make_float4(0.f, 0.f, 0.f, 0.f);
    for (int sp = 0; sp < QT_SPLITS; sp++) {
        const float4* qp = reinterpret_cast<const float4*>(g_qt_part)
                           + (size_t)(sp * B + b) * D4;
#pragma unroll
        for (int k = 0; k < 8; k++) {
            float4 v = qp[k * 32 + lane];
            q[k].x += v.x; q[k].y += v.y; q[k].z += v.z; q[k].w += v.w;
        }
    }
    float qb = 0.f;
#pragma unroll
    for (int sp = 0; sp < 16; sp++) qb += g_qbk_part[sp * 16 + b];

    float4 acc[8];
#pragma unroll
    for (int k = 0; k < 8; k++) acc[k] = make_float4(0.f, 0.f, 0.f, 0.f);
    float Ew = 0.f;

    // ---- mainloop (R4-validated): wait<2> / sync / read / sync / refill ----
    for (int i = 0; i < nst; i++) {
        int s = (st0 + i) * STAGE_ROWS + warp;
        float twv = g_tw[b * S + s];          // off the critical chain

        if (issued < nst) cp_wait<DEPTH - 1>(); else cp_wait<0>();
        __syncthreads();

        const float4* vp = sbuf + ((size_t)(i % DEPTH) * STAGE_ROWS + warp) * D4;
        float4 v[8];
#pragma unroll
        for (int k = 0; k < 8; k++) v[k] = vp[k * 32 + lane];
        __syncthreads();                 // slot consumed -> free for refill

        // refill the freed slot BEFORE the long compute chain
        if (issued < nst) {
            uint32_t dst = sb + (uint32_t)(issued % DEPTH) * STAGE_BYTES;
            const float* src = gsrc + (size_t)issued * STAGE_ROWS * D;
            for (int c = tid; c < STAGE_F4; c += 256)
                cp_async16(dst + (uint32_t)c * 16, src + (size_t)c * 4);
            cp_commit();
            issued++;
        }

        float d0 = 0.f, d1 = 0.f, d2 = 0.f, d3 = 0.f;
#pragma unroll
        for (int k = 0; k < 8; k++) {
            d0 += v[k].x * q[k].x; d1 += v[k].y * q[k].y;
            d2 += v[k].z * q[k].z; d3 += v[k].w * q[k].w;
        }
        float ds = (d0 + d1) + (d2 + d3);
#pragma unroll
        for (int o = 16; o > 0; o >>= 1) ds += __shfl_xor_sync(0xffffffffu, ds, o);

        float p = __expf((ds + qb) * 0.03125f * twv);
        if (lane == 0) g_p[b * S + s] = p;
        Ew += p;
#pragma unroll
        for (int k = 0; k < 8; k++) {
            acc[k].x += p * v[k].x; acc[k].y += p * v[k].y;
            acc[k].z += p * v[k].z; acc[k].w += p * v[k].w;
        }
    }

    // ---- epilogue (R4): cross-warp reduce, write macc/Epart, exit ----
    cp_wait<0>();
    __syncthreads();
    float4* red = sbuf;
#pragma unroll
    for (int k = 0; k < 8; k++)
        red[(size_t)warp * D4 + k * 32 + lane] = acc[k];
    if (lane == 0) sE[warp] = Ew;
    __syncthreads();

    float4 r = red[tid];
#pragma unroll
    for (int w = 1; w < 8; w++) {
        float4 v = red[(size_t)w * D4 + tid];
        r.x += v.x; r.y += v.y; r.z += v.z; r.w += v.w;
    }
    reinterpret_cast<float4*>(g_macc)[(size_t)blockIdx.x * D4 + tid] = r;
    if (tid == 0) {
        float e = 0.f;
#pragma unroll
        for (int w = 0; w < 8; w++) e += sE[w];
        g_Epart[blockIdx.x] = e;
    }
}

// ============================================================
// k_mid: 80 blocks x 256 threads, NO dynamic smem.
//   bid 0..15 : m-role — m[b] = (sum_c macc[b,c]) / E.
//   bid 16..79: attn-role — b=(bid-16)>>2, quarter=(bid-16)&3:
//               inv = 1/E (redundant warp-reduce), attn = p*inv.
// ============================================================
__global__ __launch_bounds__(256) void k_mid(float* __restrict__ attn)
{
    __shared__ float sInv;
    int bid = blockIdx.x;
    int tid = threadIdx.x, lane = tid & 31;

    if (bid < 16) {
        int b = bid;
        if (tid < 32) {
            float e = (lane < CTAS_PER_B) ? g_Epart[b * CTAS_PER_B + lane] : 0.f;
#pragma unroll
            for (int o = 16; o > 0; o >>= 1)
                e += __shfl_xor_sync(0xffffffffu, e, o);
            if (lane == 0) sInv = 1.f / e;
        }
        __syncthreads();
        float inv = sInv;

        const float4* mp = reinterpret_cast<const float4*>(g_macc);
        float4 a = make_float4(0.f, 0.f, 0.f, 0.f);
#pragma unroll
        for (int c = 0; c < CTAS_PER_B; c++) {
            float4 v = mp[(size_t)(b * CTAS_PER_B + c) * D4 + tid];
            a.x += v.x; a.y += v.y; a.z += v.z; a.w += v.w;
        }
        a.x *= inv; a.y *= inv; a.z *= inv; a.w *= inv;
        reinterpret_cast<float4*>(g_m)[b * D4 + tid] = a;
    } else {
        int q = bid - 16;
        int b = q >> 2, quarter = q & 3;

        if (tid < 32) {
            float e = (lane < CTAS_PER_B) ? g_Epart[b * CTAS_PER_B + lane] : 0.f;
#pragma unroll
            for (int o = 16; o > 0; o >>= 1)
                e += __shfl_xor_sync(0xffffffffu, e, o);
            if (lane == 0) sInv = 1.f / e;
        }
        __syncthreads();
        float inv = sInv;

        int s = quarter * 1024 + tid * 4;
        float4 p = *reinterpret_cast<const float4*>(g_p + b * S + s);
        p.x *= inv; p.y *= inv; p.z *= inv; p.w *= inv;
        *reinterpret_cast<float4*>(attn + b * S + s) = p;
    }
}

// ============================================================
// k_fin: 128 blocks x 256 threads. attended[b,d] = m[b].Wv[d] + bv[d].
// Hoisted Wv loads; m staged in smem; 16 accumulators; one reduce phase.
// ============================================================
__global__ __launch_bounds__(256) void k_fin(
    const float* __restrict__ Wv, const float* __restrict__ bv,
    float* __restrict__ attended)
{
    extern __shared__ __align__(16) float4 ms4[];   // [B][256] = 64 KB
    int tid = threadIdx.x;
    int warp = tid >> 5, lane = tid & 31;
    int d = blockIdx.x * 8 + warp;

    const float4* W4 = reinterpret_cast<const float4*>(Wv) + (size_t)d * D4;
    float4 w[8];
#pragma unroll
    for (int ch = 0; ch < 8; ch++) w[ch] = W4[ch * 32 + lane];

    const float4* gm4 = reinterpret_cast<const float4*>(g_m);
    for (int i = tid; i < B * D4; i += 256) ms4[i] = gm4[i];
    __syncthreads();

    float acc[16];
#pragma unroll
    for (int bb = 0; bb < 16; bb++) acc[bb] = 0.f;

#pragma unroll
    for (int ch = 0; ch < 8; ch++) {
#pragma unroll
        for (int bb = 0; bb < 16; bb++) {
            float4 m = ms4[bb * D4 + ch * 32 + lane];
            acc[bb] += m.x * w[ch].x + m.y * w[ch].y
                     + m.z * w[ch].z + m.w * w[ch].w;
        }
    }

#pragma unroll
    for (int o = 16; o > 0; o >>= 1) {
#pragma unroll
        for (int bb = 0; bb < 16; bb++)
            acc[bb] += __shfl_xor_sync(0xffffffffu, acc[bb], o);
    }
    if (lane == 0) {
        float bb_ = bv[d];
#pragma unroll
        for (int bb = 0; bb < 16; bb++)
            attended[bb * D + d] = acc[bb] + bb_;
    }
}

// ============================================================
extern "C" void kernel_launch(void* const* d_in, const int* in_sizes, int n_in,
                              void* d_out, int out_size)
{
    const float* query = (const float*)d_in[0];
    const float* mb    = (const float*)d_in[1];
    const float* ts    = (const float*)d_in[2];
    const float* ct    = (const float*)d_in[3];
    const float* Wq    = (const float*)d_in[4];
    const float* bq    = (const float*)d_in[5];
    const float* Wk    = (const float*)d_in[6];
    const float* bk    = (const float*)d_in[7];
    const float* Wv    = (const float*)d_in[8];
    const float* bv    = (const float*)d_in[9];
    (void)in_sizes; (void)n_in; (void)out_size;

    float* attended = (float*)d_out;            // [16,1024]
    float* attn     = (float*)d_out + B * D;    // [16,4096]

    cudaFuncSetAttribute(k_main, cudaFuncAttributeMaxDynamicSharedMemorySize,
                         SMEM_MAIN);
    cudaFuncSetAttribute(k_fin, cudaFuncAttributeMaxDynamicSharedMemorySize,
                         SMEM_FIN);

    k_qt2<<<128, 256>>>(query, Wq, Wk, bq, bk, ts, ct); // 1: Q+qt+qbk+tw
    k_main<<<NCTA_MAIN, 256, SMEM_MAIN>>>(mb);          // 2: 268 MB pass
    k_mid<<<80, 256>>>(attn);                           // 3: m + attn
    k_fin<<<128, 256, SMEM_FIN>>>(Wv, bv, attended);    // 4: attended
}